// round 8
// baseline (speedup 1.0000x reference)
#include <cuda_runtime.h>

// NeuralCDE: B=1024 RK4(3/8) recurrences, 127 steps, 4 F-evals/step.
// 128 CTAs x 256 threads, 8 batch rows per CTA, 4 W2-cols per thread.
// mm2: fma.rn.f32x2, K packed into lanes; W2 conflict-free k-pair layout + reg tail.
// mm1: warp-cooperative (warp owns 8 cols x 8 rows) -> W1 read once per CTA.
// zp/zn fused into mm2 epilogue (quad-leader threads) -> 9 barriers/step.

#define NB   1024
#define NT   128
#define NI   16
#define NHID 64
#define NOUT 10
#define MR   8
#define NCTA (NB / MR)      // 128
#define NTHR 256
#define KSM  44             // W2 rows held in SMEM (22 k-pairs)
#define KRG  20             // W2 rows held in registers (10 k-pairs)
#define NQS  (KSM / 4)      // 11 quad iterations (2 k-pairs each)
#define NQR  (KRG / 4)      // 5
#define ZP   68             // padded row stride for z / zp_ / w1t
#define HP   68             // padded row stride for h (conflict-free stores)

struct __align__(16) SM {
    float w2[KSM * 1024];   // 180224 B  [kp][half][t][{c0k0,c0k1,c1k0,c1k1}]
    float w1t[64 * ZP];     //  17408 B  [col][k] padded
    float b2[1024];         //   4096 B
    float wlin[640];        //   2560 B
    float blin[16];         //     64 B
    float b1[64];           //    256 B
    float z[8 * ZP];        //   2176 B  [row][k] padded
    float zp_[8 * ZP];      //   2176 B
    float ks[4][512];       //   8192 B  [ss][row*64+hid] (also W_init scratch at init)
    float h[8 * HP];        //   2176 B  [row][k] padded
    float dx[4 * 8 * 16];   //   2048 B  [substep][row][ch]
};                          // total ~221376 B (<= 232448 max dyn smem)

static __device__ __forceinline__ unsigned long long pk(float a, float b) {
    unsigned long long r;
    asm("mov.b64 %0, {%1, %2};" : "=l"(r) : "f"(a), "f"(b));
    return r;
}
static __device__ __forceinline__ void upk(unsigned long long u, float& a, float& b) {
    asm("mov.b64 {%0, %1}, %2;" : "=f"(a), "=f"(b) : "l"(u));
}
static __device__ __forceinline__ void fma2(unsigned long long& d,
                                            unsigned long long a,
                                            unsigned long long b) {
    asm("fma.rn.f32x2 %0, %1, %2, %0;" : "+l"(d) : "l"(a), "l"(b));
}
// tanh(x) = 1 - 2/(exp(2x)+1); ex2/rcp approx -> ~1e-6 abs err, saturates correctly.
static __device__ __forceinline__ float tanh_fast(float x) {
    float e, r;
    asm("ex2.approx.f32 %0, %1;" : "=f"(e) : "f"(x * 2.8853900817779268f));
    asm("rcp.approx.f32 %0, %1;" : "=f"(r) : "f"(e + 1.0f));
    return fmaf(-2.0f, r, 1.0f);
}

__global__ void __launch_bounds__(NTHR, 1)
cde_kernel(const float* __restrict__ ca, const float* __restrict__ cb,
           const float* __restrict__ cc, const float* __restrict__ cd,
           const float* __restrict__ Wi, const float* __restrict__ bi,
           const float* __restrict__ W1, const float* __restrict__ b1g,
           const float* __restrict__ W2, const float* __restrict__ b2g,
           const float* __restrict__ Wl, const float* __restrict__ blg,
           float* __restrict__ out) {
    extern __shared__ __align__(16) char smraw[];
    SM* s = (SM*)smraw;
    const int t  = threadIdx.x;
    const int b0 = blockIdx.x * MR;

    // ---- W2 register tail: rows 44..63, this thread's 4 cols (4t..4t+3), k-paired ----
    unsigned long long wr[KRG / 2][4];
#pragma unroll
    for (int p = 0; p < KRG / 2; p++) {
        float4 a = *(const float4*)(W2 + (size_t)(KSM + 2 * p) * 1024 + 4 * t);
        float4 b = *(const float4*)(W2 + (size_t)(KSM + 2 * p + 1) * 1024 + 4 * t);
        wr[p][0] = pk(a.x, b.x);
        wr[p][1] = pk(a.y, b.y);
        wr[p][2] = pk(a.z, b.z);
        wr[p][3] = pk(a.w, b.w);
    }
    // ---- stage weights into SMEM ----
    {
        // W2 rows 0..43: per k-pair kp = k>>1, two 4KB halves, 16B per thread per half.
        for (int i = t; i < KSM * 256; i += NTHR) {
            int k = i >> 8, q = i & 255;
            float4 v = ((const float4*)W2)[i];
            float* d = s->w2 + (k >> 1) * 2048 + q * 4 + (k & 1);
            d[0]    = v.x;  d[2]    = v.y;
            d[1024] = v.z;  d[1026] = v.w;
        }
        // W1 transposed padded: w1t[c*ZP + k] = W1[k][c]
        for (int i = t; i < 4096; i += NTHR) {
            int k = i >> 6, c = i & 63;
            s->w1t[c * ZP + k] = W1[i];
        }
        ((float4*)s->b2)[t] = ((const float4*)b2g)[t];
        if (t < 160) ((float4*)s->wlin)[t] = ((const float4*)Wl)[t];
        if (t < NOUT) s->blin[t] = blg[t];
        if (t < 64) s->b1[t] = b1g[t];
        // W_init (1024 floats) into ks scratch
        ((float4*)s->ks[0])[t] = ((const float4*)Wi)[t];
        // coeff_a[:,0] (8x16) into dx[0] scratch
        if (t < 128) {
            int r = t >> 4, i = t & 15;
            s->dx[r * 16 + i] = ca[((size_t)(b0 + r) * 127 + 0) * 16 + i];
        }
    }
    __syncthreads();

    // ---- z0 = coeff_a[:,0] @ W_init + b_init ----
#pragma unroll
    for (int e = 0; e < 2; e++) {
        int idx = t + e * 256;
        int r = idx >> 6, hid = idx & 63;
        float a = bi[hid];
#pragma unroll
        for (int i = 0; i < 16; i++) a = fmaf(s->dx[r * 16 + i], s->ks[0][i * 64 + hid], a);
        s->z[r * ZP + hid] = a;
    }
    __syncthreads();

    // ================= main time loop =================
    for (int j = 0; j < NT - 1; j++) {
        // Phase A: t>=128 load coeffs & build dX; t<80 emit output row j (z is stable).
        if (t >= 128) {
            int q = t - 128;
            int r = q >> 4, i = q & 15;
            size_t base = ((size_t)(b0 + r) * 127 + j) * 16 + i;
            float bb = cb[base], c2 = cc[base], d3 = cd[base];
            float old3 = s->dx[(3 * 8 + r) * 16 + i];
            float fj = (float)j;
            float f1 = (fj + (1.0f / 3.0f)) - fj;   // matches reference fp32 frac
            float f2 = (fj + (2.0f / 3.0f)) - fj;
            s->dx[(0 * 8 + r) * 16 + i] = (j == 0) ? bb : old3;  // k1: prev interval, frac=1
            s->dx[(1 * 8 + r) * 16 + i] = fmaf(fmaf(d3, f1, c2), f1, bb);
            s->dx[(2 * 8 + r) * 16 + i] = fmaf(fmaf(d3, f2, c2), f2, bb);
            s->dx[(3 * 8 + r) * 16 + i] = bb + (c2 + d3);        // frac=1
        } else if (t < 80) {
            int r = t / 10, o = t % 10;
            float a = s->blin[o];
#pragma unroll 8
            for (int kk = 0; kk < 64; kk++) a = fmaf(s->z[r * ZP + kk], s->wlin[kk * 10 + o], a);
            out[((size_t)(b0 + r) * NT + j) * NOUT + o] = a;
        }
        __syncthreads();

        // ---- four RK4(3/8) substeps ----
#pragma unroll 1
        for (int ss = 0; ss < 4; ss++) {
            const float* zin = (ss == 0) ? s->z : s->zp_;

            // ---- mm1: h = relu(z' @ W1 + b1); warp w -> cols 8w..8w+7, rows (r0, r0+4) ----
            {
                int w = t >> 5, lane = t & 31;
                int c = (w << 3) + (lane & 7);
                int r0 = lane >> 3;                 // 0..3
                const float* zr0 = zin + r0 * ZP;
                const float* zr1 = zin + (r0 + 4) * ZP;
                const float* wc = s->w1t + c * ZP;
                float a0 = s->b1[c], a1 = a0;
#pragma unroll
                for (int q = 0; q < 16; q++) {
                    float4 wq = *(const float4*)(wc + 4 * q);
                    float4 z0 = *(const float4*)(zr0 + 4 * q);
                    float4 z1 = *(const float4*)(zr1 + 4 * q);
                    a0 = fmaf(z0.x, wq.x, a0); a0 = fmaf(z0.y, wq.y, a0);
                    a0 = fmaf(z0.z, wq.z, a0); a0 = fmaf(z0.w, wq.w, a0);
                    a1 = fmaf(z1.x, wq.x, a1); a1 = fmaf(z1.y, wq.y, a1);
                    a1 = fmaf(z1.z, wq.z, a1); a1 = fmaf(z1.w, wq.w, a1);
                }
                s->h[r0 * HP + c]       = fmaxf(a0, 0.0f);
                s->h[(r0 + 4) * HP + c] = fmaxf(a1, 0.0f);
            }
            __syncthreads();

            // ---- mm2: g = h @ W2 + b2, cols 4t..4t+3, 8 rows ----
            unsigned long long acc[4][8];
            {
                float4 bv = *(const float4*)(s->b2 + 4 * t);
                unsigned long long q0 = pk(bv.x, 0.0f), q1 = pk(bv.y, 0.0f);
                unsigned long long q2 = pk(bv.z, 0.0f), q3 = pk(bv.w, 0.0f);
#pragma unroll
                for (int r = 0; r < 8; r++) {
                    acc[0][r] = q0; acc[1][r] = q1; acc[2][r] = q2; acc[3][r] = q3;
                }
            }
#pragma unroll 2
            for (int kq = 0; kq < NQS; kq++) {
                const float* wp = s->w2 + (size_t)(2 * kq) * 2048 + 4 * t;
                ulonglong2 wA = *(const ulonglong2*)(wp);          // kp0: cols 0,1
                ulonglong2 wB = *(const ulonglong2*)(wp + 1024);   // kp0: cols 2,3
                ulonglong2 wC = *(const ulonglong2*)(wp + 2048);   // kp1: cols 0,1
                ulonglong2 wD = *(const ulonglong2*)(wp + 3072);   // kp1: cols 2,3
#pragma unroll
                for (int r = 0; r < 8; r++) {
                    ulonglong2 hv = *(const ulonglong2*)(s->h + r * HP + 4 * kq);
                    fma2(acc[0][r], hv.x, wA.x);
                    fma2(acc[1][r], hv.x, wA.y);
                    fma2(acc[2][r], hv.x, wB.x);
                    fma2(acc[3][r], hv.x, wB.y);
                    fma2(acc[0][r], hv.y, wC.x);
                    fma2(acc[1][r], hv.y, wC.y);
                    fma2(acc[2][r], hv.y, wD.x);
                    fma2(acc[3][r], hv.y, wD.y);
                }
            }
            // register tail: rows 44..63, zero smem w-traffic
#pragma unroll
            for (int qq = 0; qq < NQR; qq++) {
                const int p0 = 2 * qq, p1i = 2 * qq + 1;
#pragma unroll
                for (int r = 0; r < 8; r++) {
                    ulonglong2 hv = *(const ulonglong2*)(s->h + r * HP + KSM + 4 * qq);
                    fma2(acc[0][r], hv.x, wr[p0][0]);
                    fma2(acc[1][r], hv.x, wr[p0][1]);
                    fma2(acc[2][r], hv.x, wr[p0][2]);
                    fma2(acc[3][r], hv.x, wr[p0][3]);
                    fma2(acc[0][r], hv.y, wr[p1i][0]);
                    fma2(acc[1][r], hv.y, wr[p1i][1]);
                    fma2(acc[2][r], hv.y, wr[p1i][2]);
                    fma2(acc[3][r], hv.y, wr[p1i][3]);
                }
            }
            // ---- epilogue: fold + tanh + einsum + butterfly; leaders write ks AND z'/z ----
            {
                int i0 = (t & 3) * 4, hc = t >> 2;
                const bool lead = (t & 3) == 0;
#pragma unroll
                for (int r = 0; r < 8; r++) {
                    float4 dxv = *(const float4*)(s->dx + (ss * 8 + r) * 16 + i0);
                    float e0, o0, e1, o1, e2, o2, e3, o3;
                    upk(acc[0][r], e0, o0);
                    upk(acc[1][r], e1, o1);
                    upk(acc[2][r], e2, o2);
                    upk(acc[3][r], e3, o3);
                    float p = tanh_fast(e0 + o0) * dxv.x + tanh_fast(e1 + o1) * dxv.y
                            + tanh_fast(e2 + o2) * dxv.z + tanh_fast(e3 + o3) * dxv.w;
                    p += __shfl_xor_sync(0xffffffffu, p, 1);
                    p += __shfl_xor_sync(0xffffffffu, p, 2);
                    if (lead) {
                        int zi = r * ZP + hc, ki = r * 64 + hc;
                        float zv = s->z[zi];
                        if (ss == 0) {
                            s->ks[0][ki] = p;
                            s->zp_[zi] = fmaf(p, (1.0f / 3.0f), zv);
                        } else if (ss == 1) {
                            s->ks[1][ki] = p;
                            s->zp_[zi] = zv + p - s->ks[0][ki] * (1.0f / 3.0f);
                        } else if (ss == 2) {
                            s->ks[2][ki] = p;
                            s->zp_[zi] = zv + s->ks[0][ki] - s->ks[1][ki] + p;
                        } else {
                            float d = s->ks[0][ki] + 3.0f * (s->ks[1][ki] + s->ks[2][ki]) + p;
                            s->z[zi] = fmaf(d, 0.125f, zv);
                        }
                    }
                }
            }
            __syncthreads();
        }
    }
    // ---- final output row t = 127 ----
    if (t < 80) {
        int r = t / 10, o = t % 10;
        float a = s->blin[o];
#pragma unroll 8
        for (int kk = 0; kk < 64; kk++) a = fmaf(s->z[r * ZP + kk], s->wlin[kk * 10 + o], a);
        out[((size_t)(b0 + r) * NT + (NT - 1)) * NOUT + o] = a;
    }
}

extern "C" void kernel_launch(void* const* d_in, const int* in_sizes, int n_in,
                              void* d_out, int out_size) {
    // metadata order: times, coeff_a, coeff_b, coeff_two_c, coeff_three_d,
    //                 final_index, W_init, b_init, W1, b1, W2, b2, W_lin, b_lin
    const float* ca = (const float*)d_in[1];
    const float* cb = (const float*)d_in[2];
    const float* cc = (const float*)d_in[3];
    const float* cd = (const float*)d_in[4];
    const float* Wi = (const float*)d_in[6];
    const float* bi = (const float*)d_in[7];
    const float* W1 = (const float*)d_in[8];
    const float* b1 = (const float*)d_in[9];
    const float* W2 = (const float*)d_in[10];
    const float* b2 = (const float*)d_in[11];
    const float* Wl = (const float*)d_in[12];
    const float* bl = (const float*)d_in[13];
    float* out = (float*)d_out;

    size_t smem = sizeof(SM);
    cudaFuncSetAttribute(cde_kernel, cudaFuncAttributeMaxDynamicSharedMemorySize, (int)smem);
    cde_kernel<<<NCTA, NTHR, smem>>>(ca, cb, cc, cd, Wi, bi, W1, b1, W2, b2, Wl, bl, out);
}

// round 9
// speedup vs baseline: 1.1177x; 1.1177x over previous
#include <cuda_runtime.h>

// NeuralCDE: B=1024 RK4(3/8) recurrences, 127 steps, 4 F-evals/step.
// 128 CTAs x 256 threads, 8 batch rows per CTA, 4 W2-cols per thread.
// mm2: fma.rn.f32x2, K packed into lanes; W2 conflict-free k-pair layout + reg tail.
// mm1: warp-cooperative (warp owns 8 cols x 8 rows) -> W1 read once per CTA,
//      all mm1 LDS.128 single-wavefront. zp/zn: separate fully-parallel phases.

#define NB   1024
#define NT   128
#define NI   16
#define NHID 64
#define NOUT 10
#define MR   8
#define NCTA (NB / MR)      // 128
#define NTHR 256
#define KSM  44             // W2 rows held in SMEM (22 k-pairs)
#define KRG  20             // W2 rows held in registers (10 k-pairs)
#define NQS  (KSM / 4)      // 11 quad iterations (2 k-pairs each)
#define NQR  (KRG / 4)      // 5
#define ZP   68             // padded row stride for z / zp_ / w1t
#define HP   68             // padded row stride for h (conflict-free stores)

struct __align__(16) SM {
    float w2[KSM * 1024];   // 180224 B  [kp][half][t][{c0k0,c0k1,c1k0,c1k1}]
    float w1t[64 * ZP];     //  17408 B  [col][k] padded
    float b2[1024];         //   4096 B
    float wlin[640];        //   2560 B
    float blin[16];         //     64 B
    float b1[64];           //    256 B
    float z[8 * ZP];        //   2176 B  [row][k] padded
    float zp_[8 * ZP];      //   2176 B
    float ks[4][512];       //   8192 B  [ss][row*64+hid] (also W_init scratch at init)
    float h[8 * HP];        //   2176 B  [row][k] padded
    float dx[4 * 8 * 16];   //   2048 B  [substep][row][ch]
};                          // total ~221376 B (<= 232448 max dyn smem)

static __device__ __forceinline__ unsigned long long pk(float a, float b) {
    unsigned long long r;
    asm("mov.b64 %0, {%1, %2};" : "=l"(r) : "f"(a), "f"(b));
    return r;
}
static __device__ __forceinline__ void upk(unsigned long long u, float& a, float& b) {
    asm("mov.b64 {%0, %1}, %2;" : "=f"(a), "=f"(b) : "l"(u));
}
static __device__ __forceinline__ void fma2(unsigned long long& d,
                                            unsigned long long a,
                                            unsigned long long b) {
    asm("fma.rn.f32x2 %0, %1, %2, %0;" : "+l"(d) : "l"(a), "l"(b));
}
// tanh(x) = 1 - 2/(exp(2x)+1); ex2/rcp approx -> ~1e-6 abs err, saturates correctly.
static __device__ __forceinline__ float tanh_fast(float x) {
    float e, r;
    asm("ex2.approx.f32 %0, %1;" : "=f"(e) : "f"(x * 2.8853900817779268f));
    asm("rcp.approx.f32 %0, %1;" : "=f"(r) : "f"(e + 1.0f));
    return fmaf(-2.0f, r, 1.0f);
}

__global__ void __launch_bounds__(NTHR, 1)
cde_kernel(const float* __restrict__ ca, const float* __restrict__ cb,
           const float* __restrict__ cc, const float* __restrict__ cd,
           const float* __restrict__ Wi, const float* __restrict__ bi,
           const float* __restrict__ W1, const float* __restrict__ b1g,
           const float* __restrict__ W2, const float* __restrict__ b2g,
           const float* __restrict__ Wl, const float* __restrict__ blg,
           float* __restrict__ out) {
    extern __shared__ __align__(16) char smraw[];
    SM* s = (SM*)smraw;
    const int t  = threadIdx.x;
    const int b0 = blockIdx.x * MR;

    // ---- W2 register tail: rows 44..63, this thread's 4 cols (4t..4t+3), k-paired ----
    unsigned long long wr[KRG / 2][4];
#pragma unroll
    for (int p = 0; p < KRG / 2; p++) {
        float4 a = *(const float4*)(W2 + (size_t)(KSM + 2 * p) * 1024 + 4 * t);
        float4 b = *(const float4*)(W2 + (size_t)(KSM + 2 * p + 1) * 1024 + 4 * t);
        wr[p][0] = pk(a.x, b.x);
        wr[p][1] = pk(a.y, b.y);
        wr[p][2] = pk(a.z, b.z);
        wr[p][3] = pk(a.w, b.w);
    }
    // ---- stage weights into SMEM ----
    {
        // W2 rows 0..43: per k-pair kp = k>>1, two 4KB halves, 16B per thread per half.
        for (int i = t; i < KSM * 256; i += NTHR) {
            int k = i >> 8, q = i & 255;
            float4 v = ((const float4*)W2)[i];
            float* d = s->w2 + (k >> 1) * 2048 + q * 4 + (k & 1);
            d[0]    = v.x;  d[2]    = v.y;
            d[1024] = v.z;  d[1026] = v.w;
        }
        // W1 transposed padded: w1t[c*ZP + k] = W1[k][c]
        for (int i = t; i < 4096; i += NTHR) {
            int k = i >> 6, c = i & 63;
            s->w1t[c * ZP + k] = W1[i];
        }
        ((float4*)s->b2)[t] = ((const float4*)b2g)[t];
        if (t < 160) ((float4*)s->wlin)[t] = ((const float4*)Wl)[t];
        if (t < NOUT) s->blin[t] = blg[t];
        if (t < 64) s->b1[t] = b1g[t];
        // W_init (1024 floats) into ks scratch
        ((float4*)s->ks[0])[t] = ((const float4*)Wi)[t];
        // coeff_a[:,0] (8x16) into dx[0] scratch
        if (t < 128) {
            int r = t >> 4, i = t & 15;
            s->dx[r * 16 + i] = ca[((size_t)(b0 + r) * 127 + 0) * 16 + i];
        }
    }
    __syncthreads();

    // ---- z0 = coeff_a[:,0] @ W_init + b_init ----
#pragma unroll
    for (int e = 0; e < 2; e++) {
        int idx = t + e * 256;
        int r = idx >> 6, hid = idx & 63;
        float a = bi[hid];
#pragma unroll
        for (int i = 0; i < 16; i++) a = fmaf(s->dx[r * 16 + i], s->ks[0][i * 64 + hid], a);
        s->z[r * ZP + hid] = a;
    }
    __syncthreads();

    // ================= main time loop =================
    for (int j = 0; j < NT - 1; j++) {
        // Phase A: t>=128 load coeffs & build dX; t<80 emit output row j.
        if (t >= 128) {
            int q = t - 128;
            int r = q >> 4, i = q & 15;
            size_t base = ((size_t)(b0 + r) * 127 + j) * 16 + i;
            float bb = cb[base], c2 = cc[base], d3 = cd[base];
            float old3 = s->dx[(3 * 8 + r) * 16 + i];
            float fj = (float)j;
            float f1 = (fj + (1.0f / 3.0f)) - fj;   // matches reference fp32 frac
            float f2 = (fj + (2.0f / 3.0f)) - fj;
            s->dx[(0 * 8 + r) * 16 + i] = (j == 0) ? bb : old3;  // k1: prev interval, frac=1
            s->dx[(1 * 8 + r) * 16 + i] = fmaf(fmaf(d3, f1, c2), f1, bb);
            s->dx[(2 * 8 + r) * 16 + i] = fmaf(fmaf(d3, f2, c2), f2, bb);
            s->dx[(3 * 8 + r) * 16 + i] = bb + (c2 + d3);        // frac=1
        } else if (t < 80) {
            int r = t / 10, o = t % 10;
            float a = s->blin[o];
#pragma unroll 8
            for (int kk = 0; kk < 64; kk++) a = fmaf(s->z[r * ZP + kk], s->wlin[kk * 10 + o], a);
            out[((size_t)(b0 + r) * NT + j) * NOUT + o] = a;
        }
        __syncthreads();

        // ---- four RK4(3/8) substeps ----
#pragma unroll 1
        for (int ss = 0; ss < 4; ss++) {
            const float* zin = s->z;
            if (ss > 0) {
#pragma unroll
                for (int e = 0; e < 2; e++) {
                    int idx = t + e * 256;
                    int r = idx >> 6, kk = idx & 63;
                    float zv = s->z[r * ZP + kk];
                    float v;
                    if (ss == 1)      v = fmaf(s->ks[0][idx], (1.0f / 3.0f), zv);
                    else if (ss == 2) v = zv + s->ks[1][idx] - s->ks[0][idx] * (1.0f / 3.0f);
                    else              v = zv + s->ks[0][idx] - s->ks[1][idx] + s->ks[2][idx];
                    s->zp_[r * ZP + kk] = v;
                }
                __syncthreads();
                zin = s->zp_;
            }
            // ---- mm1: h = relu(z' @ W1 + b1); warp w -> cols 8w..8w+7, rows (r0, r0+4) ----
            {
                int w = t >> 5, lane = t & 31;
                int c = (w << 3) + (lane & 7);
                int r0 = lane >> 3;                 // 0..3
                const float* zr0 = zin + r0 * ZP;
                const float* zr1 = zin + (r0 + 4) * ZP;
                const float* wc = s->w1t + c * ZP;
                float a0 = s->b1[c], a1 = a0;
#pragma unroll
                for (int q = 0; q < 16; q++) {
                    float4 wq = *(const float4*)(wc + 4 * q);
                    float4 z0 = *(const float4*)(zr0 + 4 * q);
                    float4 z1 = *(const float4*)(zr1 + 4 * q);
                    a0 = fmaf(z0.x, wq.x, a0); a0 = fmaf(z0.y, wq.y, a0);
                    a0 = fmaf(z0.z, wq.z, a0); a0 = fmaf(z0.w, wq.w, a0);
                    a1 = fmaf(z1.x, wq.x, a1); a1 = fmaf(z1.y, wq.y, a1);
                    a1 = fmaf(z1.z, wq.z, a1); a1 = fmaf(z1.w, wq.w, a1);
                }
                s->h[r0 * HP + c]       = fmaxf(a0, 0.0f);
                s->h[(r0 + 4) * HP + c] = fmaxf(a1, 0.0f);
            }
            __syncthreads();

            // ---- mm2: g = h @ W2 + b2, cols 4t..4t+3, 8 rows ----
            unsigned long long acc[4][8];
            {
                float4 bv = *(const float4*)(s->b2 + 4 * t);
                unsigned long long q0 = pk(bv.x, 0.0f), q1 = pk(bv.y, 0.0f);
                unsigned long long q2 = pk(bv.z, 0.0f), q3 = pk(bv.w, 0.0f);
#pragma unroll
                for (int r = 0; r < 8; r++) {
                    acc[0][r] = q0; acc[1][r] = q1; acc[2][r] = q2; acc[3][r] = q3;
                }
            }
#pragma unroll 2
            for (int kq = 0; kq < NQS; kq++) {
                const float* wp = s->w2 + (size_t)(2 * kq) * 2048 + 4 * t;
                ulonglong2 wA = *(const ulonglong2*)(wp);          // kp0: cols 0,1
                ulonglong2 wB = *(const ulonglong2*)(wp + 1024);   // kp0: cols 2,3
                ulonglong2 wC = *(const ulonglong2*)(wp + 2048);   // kp1: cols 0,1
                ulonglong2 wD = *(const ulonglong2*)(wp + 3072);   // kp1: cols 2,3
#pragma unroll
                for (int r = 0; r < 8; r++) {
                    ulonglong2 hv = *(const ulonglong2*)(s->h + r * HP + 4 * kq);
                    fma2(acc[0][r], hv.x, wA.x);
                    fma2(acc[1][r], hv.x, wA.y);
                    fma2(acc[2][r], hv.x, wB.x);
                    fma2(acc[3][r], hv.x, wB.y);
                    fma2(acc[0][r], hv.y, wC.x);
                    fma2(acc[1][r], hv.y, wC.y);
                    fma2(acc[2][r], hv.y, wD.x);
                    fma2(acc[3][r], hv.y, wD.y);
                }
            }
            // register tail: rows 44..63, zero smem w-traffic
#pragma unroll
            for (int qq = 0; qq < NQR; qq++) {
                const int p0 = 2 * qq, p1i = 2 * qq + 1;
#pragma unroll
                for (int r = 0; r < 8; r++) {
                    ulonglong2 hv = *(const ulonglong2*)(s->h + r * HP + KSM + 4 * qq);
                    fma2(acc[0][r], hv.x, wr[p0][0]);
                    fma2(acc[1][r], hv.x, wr[p0][1]);
                    fma2(acc[2][r], hv.x, wr[p0][2]);
                    fma2(acc[3][r], hv.x, wr[p0][3]);
                    fma2(acc[0][r], hv.y, wr[p1i][0]);
                    fma2(acc[1][r], hv.y, wr[p1i][1]);
                    fma2(acc[2][r], hv.y, wr[p1i][2]);
                    fma2(acc[3][r], hv.y, wr[p1i][3]);
                }
            }
            // ---- epilogue: fold lanes + tanh + einsum with dX + 4-lane reduce ----
            {
                int i0 = (t & 3) * 4, hc = t >> 2;
#pragma unroll
                for (int r = 0; r < 8; r++) {
                    float4 dxv = *(const float4*)(s->dx + (ss * 8 + r) * 16 + i0);
                    float e0, o0, e1, o1, e2, o2, e3, o3;
                    upk(acc[0][r], e0, o0);
                    upk(acc[1][r], e1, o1);
                    upk(acc[2][r], e2, o2);
                    upk(acc[3][r], e3, o3);
                    float p = tanh_fast(e0 + o0) * dxv.x + tanh_fast(e1 + o1) * dxv.y
                            + tanh_fast(e2 + o2) * dxv.z + tanh_fast(e3 + o3) * dxv.w;
                    p += __shfl_xor_sync(0xffffffffu, p, 1);
                    p += __shfl_xor_sync(0xffffffffu, p, 2);
                    if ((t & 3) == 0) s->ks[ss][r * 64 + hc] = p;
                }
            }
            __syncthreads();
        }
        // ---- zn = z + (k1 + 3(k2+k3) + k4)/8 ----
#pragma unroll
        for (int e = 0; e < 2; e++) {
            int idx = t + e * 256;
            int r = idx >> 6, kk = idx & 63;
            float d = s->ks[0][idx] + 3.0f * (s->ks[1][idx] + s->ks[2][idx]) + s->ks[3][idx];
            s->z[r * ZP + kk] = fmaf(d, 0.125f, s->z[r * ZP + kk]);
        }
        __syncthreads();
    }
    // ---- final output row t = 127 ----
    if (t < 80) {
        int r = t / 10, o = t % 10;
        float a = s->blin[o];
#pragma unroll 8
        for (int kk = 0; kk < 64; kk++) a = fmaf(s->z[r * ZP + kk], s->wlin[kk * 10 + o], a);
        out[((size_t)(b0 + r) * NT + (NT - 1)) * NOUT + o] = a;
    }
}

extern "C" void kernel_launch(void* const* d_in, const int* in_sizes, int n_in,
                              void* d_out, int out_size) {
    // metadata order: times, coeff_a, coeff_b, coeff_two_c, coeff_three_d,
    //                 final_index, W_init, b_init, W1, b1, W2, b2, W_lin, b_lin
    const float* ca = (const float*)d_in[1];
    const float* cb = (const float*)d_in[2];
    const float* cc = (const float*)d_in[3];
    const float* cd = (const float*)d_in[4];
    const float* Wi = (const float*)d_in[6];
    const float* bi = (const float*)d_in[7];
    const float* W1 = (const float*)d_in[8];
    const float* b1 = (const float*)d_in[9];
    const float* W2 = (const float*)d_in[10];
    const float* b2 = (const float*)d_in[11];
    const float* Wl = (const float*)d_in[12];
    const float* bl = (const float*)d_in[13];
    float* out = (float*)d_out;

    size_t smem = sizeof(SM);
    cudaFuncSetAttribute(cde_kernel, cudaFuncAttributeMaxDynamicSharedMemorySize, (int)smem);
    cde_kernel<<<NCTA, NTHR, smem>>>(ca, cb, cc, cd, Wi, bi, W1, b1, W2, b2, Wl, bl, out);
}

// round 10
// speedup vs baseline: 1.2401x; 1.1095x over previous
#include <cuda_runtime.h>

// NeuralCDE: B=1024 RK4(3/8) recurrences, 127 steps, 4 F-evals/step.
// 147 CTAs x 256 threads (one per SM), 7 batch rows per CTA (last CTA overlaps
// rows 1017..1023 with its neighbor -> duplicate identical writes, no 2nd path).
// mm2: fma.rn.f32x2, K packed into lanes; W2 conflict-free k-pair layout + reg tail.
// mm1: warp-cooperative (warp owns 8 cols) -> W1 read once per CTA.

#define NB   1024
#define NT   128
#define NI   16
#define NHID 64
#define NOUT 10
#define MR   7
#define NCTA 147
#define NTHR 256
#define KSM  44             // W2 rows held in SMEM (22 k-pairs)
#define KRG  20             // W2 rows held in registers (10 k-pairs)
#define NQS  (KSM / 4)      // 11 quad iterations (2 k-pairs each)
#define NQR  (KRG / 4)      // 5
#define ZP   68             // padded row stride for z / zp_ / w1t
#define HP   68             // padded row stride for h (conflict-free stores)

struct __align__(16) SM {
    float w2[KSM * 1024];   // 180224 B  [kp][half][t][{c0k0,c0k1,c1k0,c1k1}]
    float w1t[64 * ZP];     //  17408 B  [col][k] padded
    float b2[1024];         //   4096 B
    float wlin[640];        //   2560 B
    float blin[16];         //     64 B
    float b1[64];           //    256 B
    float z[8 * ZP];        //   2176 B  [row][k] padded (row 7 unused/garbage)
    float zp_[8 * ZP];      //   2176 B
    float ks[4][512];       //   8192 B  [ss][row*64+hid] (also W_init scratch at init)
    float h[8 * HP];        //   2176 B  [row][k] padded
    float dx[4 * 8 * 16];   //   2048 B  [substep][row][ch]
};                          // total ~221376 B (<= 232448 max dyn smem)

static __device__ __forceinline__ unsigned long long pk(float a, float b) {
    unsigned long long r;
    asm("mov.b64 %0, {%1, %2};" : "=l"(r) : "f"(a), "f"(b));
    return r;
}
static __device__ __forceinline__ void upk(unsigned long long u, float& a, float& b) {
    asm("mov.b64 {%0, %1}, %2;" : "=f"(a), "=f"(b) : "l"(u));
}
static __device__ __forceinline__ void fma2(unsigned long long& d,
                                            unsigned long long a,
                                            unsigned long long b) {
    asm("fma.rn.f32x2 %0, %1, %2, %0;" : "+l"(d) : "l"(a), "l"(b));
}
// tanh(x) = 1 - 2/(exp(2x)+1); ex2/rcp approx -> ~1e-6 abs err, saturates correctly.
static __device__ __forceinline__ float tanh_fast(float x) {
    float e, r;
    asm("ex2.approx.f32 %0, %1;" : "=f"(e) : "f"(x * 2.8853900817779268f));
    asm("rcp.approx.f32 %0, %1;" : "=f"(r) : "f"(e + 1.0f));
    return fmaf(-2.0f, r, 1.0f);
}

__global__ void __launch_bounds__(NTHR, 1)
cde_kernel(const float* __restrict__ ca, const float* __restrict__ cb,
           const float* __restrict__ cc, const float* __restrict__ cd,
           const float* __restrict__ Wi, const float* __restrict__ bi,
           const float* __restrict__ W1, const float* __restrict__ b1g,
           const float* __restrict__ W2, const float* __restrict__ b2g,
           const float* __restrict__ Wl, const float* __restrict__ blg,
           float* __restrict__ out) {
    extern __shared__ __align__(16) char smraw[];
    SM* s = (SM*)smraw;
    const int t  = threadIdx.x;
    const int b0 = (blockIdx.x == NCTA - 1) ? (NB - MR) : blockIdx.x * MR;

    // ---- W2 register tail: rows 44..63, this thread's 4 cols (4t..4t+3), k-paired ----
    unsigned long long wr[KRG / 2][4];
#pragma unroll
    for (int p = 0; p < KRG / 2; p++) {
        float4 a = *(const float4*)(W2 + (size_t)(KSM + 2 * p) * 1024 + 4 * t);
        float4 b = *(const float4*)(W2 + (size_t)(KSM + 2 * p + 1) * 1024 + 4 * t);
        wr[p][0] = pk(a.x, b.x);
        wr[p][1] = pk(a.y, b.y);
        wr[p][2] = pk(a.z, b.z);
        wr[p][3] = pk(a.w, b.w);
    }
    // ---- stage weights into SMEM ----
    {
        // W2 rows 0..43: per k-pair kp = k>>1, two 4KB halves, 16B per thread per half.
        for (int i = t; i < KSM * 256; i += NTHR) {
            int k = i >> 8, q = i & 255;
            float4 v = ((const float4*)W2)[i];
            float* d = s->w2 + (k >> 1) * 2048 + q * 4 + (k & 1);
            d[0]    = v.x;  d[2]    = v.y;
            d[1024] = v.z;  d[1026] = v.w;
        }
        // W1 transposed padded: w1t[c*ZP + k] = W1[k][c]
        for (int i = t; i < 4096; i += NTHR) {
            int k = i >> 6, c = i & 63;
            s->w1t[c * ZP + k] = W1[i];
        }
        ((float4*)s->b2)[t] = ((const float4*)b2g)[t];
        if (t < 160) ((float4*)s->wlin)[t] = ((const float4*)Wl)[t];
        if (t < NOUT) s->blin[t] = blg[t];
        if (t < 64) s->b1[t] = b1g[t];
        // W_init (1024 floats) into ks scratch
        ((float4*)s->ks[0])[t] = ((const float4*)Wi)[t];
        // coeff_a[:,0] (7x16) into dx[0] scratch
        if (t < MR * 16) {
            int r = t >> 4, i = t & 15;
            s->dx[r * 16 + i] = ca[((size_t)(b0 + r) * 127 + 0) * 16 + i];
        }
    }
    __syncthreads();

    // ---- z0 = coeff_a[:,0] @ W_init + b_init (7x64 = 448 elems) ----
#pragma unroll
    for (int e = 0; e < 2; e++) {
        int idx = t + e * 256;
        if (idx < MR * 64) {
            int r = idx >> 6, hid = idx & 63;
            float a = bi[hid];
#pragma unroll
            for (int i = 0; i < 16; i++)
                a = fmaf(s->dx[r * 16 + i], s->ks[0][i * 64 + hid], a);
            s->z[r * ZP + hid] = a;
        }
    }
    __syncthreads();

    // ================= main time loop =================
    for (int j = 0; j < NT - 1; j++) {
        // Phase A: t in [128,240) load coeffs & build dX; t<70 emit output row j.
        if (t >= 128 && t < 128 + MR * 16) {
            int q = t - 128;
            int r = q >> 4, i = q & 15;
            size_t base = ((size_t)(b0 + r) * 127 + j) * 16 + i;
            float bb = cb[base], c2 = cc[base], d3 = cd[base];
            float old3 = s->dx[(3 * 8 + r) * 16 + i];
            float fj = (float)j;
            float f1 = (fj + (1.0f / 3.0f)) - fj;   // matches reference fp32 frac
            float f2 = (fj + (2.0f / 3.0f)) - fj;
            s->dx[(0 * 8 + r) * 16 + i] = (j == 0) ? bb : old3;  // k1: prev interval, frac=1
            s->dx[(1 * 8 + r) * 16 + i] = fmaf(fmaf(d3, f1, c2), f1, bb);
            s->dx[(2 * 8 + r) * 16 + i] = fmaf(fmaf(d3, f2, c2), f2, bb);
            s->dx[(3 * 8 + r) * 16 + i] = bb + (c2 + d3);        // frac=1
        } else if (t < MR * NOUT) {
            int r = t / 10, o = t % 10;
            float a = s->blin[o];
#pragma unroll 8
            for (int kk = 0; kk < 64; kk++) a = fmaf(s->z[r * ZP + kk], s->wlin[kk * 10 + o], a);
            out[((size_t)(b0 + r) * NT + j) * NOUT + o] = a;
        }
        __syncthreads();

        // ---- four RK4(3/8) substeps ----
#pragma unroll 1
        for (int ss = 0; ss < 4; ss++) {
            const float* zin = s->z;
            if (ss > 0) {
#pragma unroll
                for (int e = 0; e < 2; e++) {
                    int idx = t + e * 256;
                    if (idx < MR * 64) {
                        int r = idx >> 6, kk = idx & 63;
                        float zv = s->z[r * ZP + kk];
                        float v;
                        if (ss == 1)      v = fmaf(s->ks[0][idx], (1.0f / 3.0f), zv);
                        else if (ss == 2) v = zv + s->ks[1][idx] - s->ks[0][idx] * (1.0f / 3.0f);
                        else              v = zv + s->ks[0][idx] - s->ks[1][idx] + s->ks[2][idx];
                        s->zp_[r * ZP + kk] = v;
                    }
                }
                __syncthreads();
                zin = s->zp_;
            }
            // ---- mm1: h = relu(z' @ W1 + b1); warp w -> cols 8w..8w+7, rows (r0, r0+4) ----
            {
                int w = t >> 5, lane = t & 31;
                int c = (w << 3) + (lane & 7);
                int r0 = lane >> 3;                 // 0..3; second row r0+4 valid iff r0<3
                const float* zr0 = zin + r0 * ZP;
                const float* zr1 = zin + (r0 + 4) * ZP;   // row 7 = garbage, discarded
                const float* wc = s->w1t + c * ZP;
                float a0 = s->b1[c], a1 = a0;
#pragma unroll
                for (int q = 0; q < 16; q++) {
                    float4 wq = *(const float4*)(wc + 4 * q);
                    float4 z0 = *(const float4*)(zr0 + 4 * q);
                    float4 z1 = *(const float4*)(zr1 + 4 * q);
                    a0 = fmaf(z0.x, wq.x, a0); a0 = fmaf(z0.y, wq.y, a0);
                    a0 = fmaf(z0.z, wq.z, a0); a0 = fmaf(z0.w, wq.w, a0);
                    a1 = fmaf(z1.x, wq.x, a1); a1 = fmaf(z1.y, wq.y, a1);
                    a1 = fmaf(z1.z, wq.z, a1); a1 = fmaf(z1.w, wq.w, a1);
                }
                s->h[r0 * HP + c] = fmaxf(a0, 0.0f);
                if (r0 < MR - 4) s->h[(r0 + 4) * HP + c] = fmaxf(a1, 0.0f);
            }
            __syncthreads();

            // ---- mm2: g = h @ W2 + b2, cols 4t..4t+3, 7 rows ----
            unsigned long long acc[4][MR];
            {
                float4 bv = *(const float4*)(s->b2 + 4 * t);
                unsigned long long q0 = pk(bv.x, 0.0f), q1 = pk(bv.y, 0.0f);
                unsigned long long q2 = pk(bv.z, 0.0f), q3 = pk(bv.w, 0.0f);
#pragma unroll
                for (int r = 0; r < MR; r++) {
                    acc[0][r] = q0; acc[1][r] = q1; acc[2][r] = q2; acc[3][r] = q3;
                }
            }
#pragma unroll 2
            for (int kq = 0; kq < NQS; kq++) {
                const float* wp = s->w2 + (size_t)(2 * kq) * 2048 + 4 * t;
                ulonglong2 wA = *(const ulonglong2*)(wp);          // kp0: cols 0,1
                ulonglong2 wB = *(const ulonglong2*)(wp + 1024);   // kp0: cols 2,3
                ulonglong2 wC = *(const ulonglong2*)(wp + 2048);   // kp1: cols 0,1
                ulonglong2 wD = *(const ulonglong2*)(wp + 3072);   // kp1: cols 2,3
#pragma unroll
                for (int r = 0; r < MR; r++) {
                    ulonglong2 hv = *(const ulonglong2*)(s->h + r * HP + 4 * kq);
                    fma2(acc[0][r], hv.x, wA.x);
                    fma2(acc[1][r], hv.x, wA.y);
                    fma2(acc[2][r], hv.x, wB.x);
                    fma2(acc[3][r], hv.x, wB.y);
                    fma2(acc[0][r], hv.y, wC.x);
                    fma2(acc[1][r], hv.y, wC.y);
                    fma2(acc[2][r], hv.y, wD.x);
                    fma2(acc[3][r], hv.y, wD.y);
                }
            }
            // register tail: rows 44..63, zero smem w-traffic
#pragma unroll
            for (int qq = 0; qq < NQR; qq++) {
                const int p0 = 2 * qq, p1i = 2 * qq + 1;
#pragma unroll
                for (int r = 0; r < MR; r++) {
                    ulonglong2 hv = *(const ulonglong2*)(s->h + r * HP + KSM + 4 * qq);
                    fma2(acc[0][r], hv.x, wr[p0][0]);
                    fma2(acc[1][r], hv.x, wr[p0][1]);
                    fma2(acc[2][r], hv.x, wr[p0][2]);
                    fma2(acc[3][r], hv.x, wr[p0][3]);
                    fma2(acc[0][r], hv.y, wr[p1i][0]);
                    fma2(acc[1][r], hv.y, wr[p1i][1]);
                    fma2(acc[2][r], hv.y, wr[p1i][2]);
                    fma2(acc[3][r], hv.y, wr[p1i][3]);
                }
            }
            // ---- epilogue: fold lanes + tanh + einsum with dX + 4-lane reduce ----
            {
                int i0 = (t & 3) * 4, hc = t >> 2;
#pragma unroll
                for (int r = 0; r < MR; r++) {
                    float4 dxv = *(const float4*)(s->dx + (ss * 8 + r) * 16 + i0);
                    float e0, o0, e1, o1, e2, o2, e3, o3;
                    upk(acc[0][r], e0, o0);
                    upk(acc[1][r], e1, o1);
                    upk(acc[2][r], e2, o2);
                    upk(acc[3][r], e3, o3);
                    float p = tanh_fast(e0 + o0) * dxv.x + tanh_fast(e1 + o1) * dxv.y
                            + tanh_fast(e2 + o2) * dxv.z + tanh_fast(e3 + o3) * dxv.w;
                    p += __shfl_xor_sync(0xffffffffu, p, 1);
                    p += __shfl_xor_sync(0xffffffffu, p, 2);
                    if ((t & 3) == 0) s->ks[ss][r * 64 + hc] = p;
                }
            }
            __syncthreads();
        }
        // ---- zn = z + (k1 + 3(k2+k3) + k4)/8 ----
#pragma unroll
        for (int e = 0; e < 2; e++) {
            int idx = t + e * 256;
            if (idx < MR * 64) {
                int r = idx >> 6, kk = idx & 63;
                float d = s->ks[0][idx] + 3.0f * (s->ks[1][idx] + s->ks[2][idx]) + s->ks[3][idx];
                s->z[r * ZP + kk] = fmaf(d, 0.125f, s->z[r * ZP + kk]);
            }
        }
        __syncthreads();
    }
    // ---- final output row t = 127 ----
    if (t < MR * NOUT) {
        int r = t / 10, o = t % 10;
        float a = s->blin[o];
#pragma unroll 8
        for (int kk = 0; kk < 64; kk++) a = fmaf(s->z[r * ZP + kk], s->wlin[kk * 10 + o], a);
        out[((size_t)(b0 + r) * NT + (NT - 1)) * NOUT + o] = a;
    }
}

extern "C" void kernel_launch(void* const* d_in, const int* in_sizes, int n_in,
                              void* d_out, int out_size) {
    // metadata order: times, coeff_a, coeff_b, coeff_two_c, coeff_three_d,
    //                 final_index, W_init, b_init, W1, b1, W2, b2, W_lin, b_lin
    const float* ca = (const float*)d_in[1];
    const float* cb = (const float*)d_in[2];
    const float* cc = (const float*)d_in[3];
    const float* cd = (const float*)d_in[4];
    const float* Wi = (const float*)d_in[6];
    const float* bi = (const float*)d_in[7];
    const float* W1 = (const float*)d_in[8];
    const float* b1 = (const float*)d_in[9];
    const float* W2 = (const float*)d_in[10];
    const float* b2 = (const float*)d_in[11];
    const float* Wl = (const float*)d_in[12];
    const float* bl = (const float*)d_in[13];
    float* out = (float*)d_out;

    size_t smem = sizeof(SM);
    cudaFuncSetAttribute(cde_kernel, cudaFuncAttributeMaxDynamicSharedMemorySize, (int)smem);
    cde_kernel<<<NCTA, NTHR, smem>>>(ca, cb, cc, cd, Wi, bi, W1, b1, W2, b2, Wl, bl, out);
}